// round 7
// baseline (speedup 1.0000x reference)
#include <cuda_runtime.h>
#include <cuda_fp16.h>
#include <cstdint>

// ============================================================================
// Fused attention via warp-level mma.sync (sm_100 base target).
//   out = softmax_causal( X * (8 Wq Wk^T) * X^T ) * X * Wv
// B=16384 batches, T=32, D=H=64, fp32 I/O.
// R7: two warps per batch (16 rows each), CTA-cooperative X staging with a
//     single __syncthreads() (no named barriers). Weight B-fragments
//     pre-packed as uint4 (one LDS.128 = hi+lo fragment pair). 3 CTAs/SM.
// ============================================================================

#define THREADS 256          // 8 warps = 4 batches per CTA
#define LDW     36           // u32 words per X smem row (72 halves)

// smem word offsets
#define W_FRAGM 0                       // 1024 uint4 = 4096 words
#define W_FRAGV 4096                    // 1024 uint4
#define W_X     8192                    // per batch: Xh 32*36 + Xl 32*36 words
#define W_PER_BATCH (2 * 32 * LDW)
#define SMEM_WORDS (W_X + 4 * W_PER_BATCH)
#define SMEM_BYTES (SMEM_WORDS * 4)     // 69632 B

// ---- weight fragment tables: frag (jt,kk) -> 32 lanes of {bh0,bh1,bl0,bl1} ----
__device__ uint4 g_fragM[1024];   // B = M8'[n][k] = 8*(Wq Wk^T)[k][n]
__device__ uint4 g_fragV[1024];   // B = Wv'[n][k] = Wv[k][n]

__device__ __forceinline__ uint32_t pack2f(float a, float b) {
    __half2 hh = __floats2half2_rn(a, b);
    return *(uint32_t*)&hh;
}

__global__ void prep_weights(const float* __restrict__ Wk, const float* __restrict__ Wq,
                             const float* __restrict__ Wv) {
    int e = blockIdx.x * blockDim.x + threadIdx.x;
    if (e >= 2048) return;
    int table = e >> 10;
    int idx   = e & 1023;
    int frag  = idx >> 5;          // jt*4 + kk
    int lane  = idx & 31;
    int jt = frag >> 2, kk = frag & 3;
    int g = lane >> 2, t = lane & 3;
    int n  = jt * 8 + g;
    int k0 = kk * 16 + 2 * t;

    float v[4];
    int ks[4] = { k0, k0 + 1, k0 + 8, k0 + 9 };
    if (table == 0) {
        #pragma unroll
        for (int i = 0; i < 4; ++i) {
            float s = 0.f;
            const float* qa = Wq + ks[i] * 64;
            const float* kb = Wk + n * 64;
            #pragma unroll
            for (int h = 0; h < 64; ++h) s = fmaf(qa[h], kb[h], s);
            v[i] = 8.0f * s;
        }
    } else {
        #pragma unroll
        for (int i = 0; i < 4; ++i) v[i] = Wv[ks[i] * 64 + n];
    }
    float hi[4], lo[4];
    #pragma unroll
    for (int i = 0; i < 4; ++i) {
        __half h = __float2half_rn(v[i]);
        hi[i] = __half2float(h);
        lo[i] = v[i] - hi[i];
    }
    uint4 out;
    out.x = pack2f(hi[0], hi[1]);
    out.y = pack2f(hi[2], hi[3]);
    out.z = pack2f(lo[0], lo[1]);
    out.w = pack2f(lo[2], lo[3]);
    (table == 0 ? g_fragM : g_fragV)[idx] = out;
}

// ---- helpers ----
#define MMA(d, a, b0, b1) asm volatile( \
    "mma.sync.aligned.m16n8k16.row.col.f32.f16.f16.f32 " \
    "{%0,%1,%2,%3}, {%4,%5,%6,%7}, {%8,%9}, {%0,%1,%2,%3};" \
    : "+f"((d)[0]), "+f"((d)[1]), "+f"((d)[2]), "+f"((d)[3]) \
    : "r"((a)[0]), "r"((a)[1]), "r"((a)[2]), "r"((a)[3]), \
      "r"(b0), "r"(b1))

__device__ __forceinline__ void split2(float a, float b, uint32_t& h, uint32_t& l) {
    __half2 hh = __floats2half2_rn(a, b);
    float2 hf = __half22float2(hh);
    __half2 ll = __floats2half2_rn(a - hf.x, b - hf.y);
    h = *(uint32_t*)&hh;
    l = *(uint32_t*)&ll;
}
__device__ __forceinline__ uint32_t packh(__half a, __half b) {
    __half2 hh = __halves2half2(a, b);
    return *(uint32_t*)&hh;
}

__global__ void __launch_bounds__(THREADS, 3)
attn_kernel(const float* __restrict__ X, float* __restrict__ Out, int nBatch)
{
    extern __shared__ uint32_t sw[];
    const int tid  = threadIdx.x;
    const int wid  = tid >> 5;
    const int lane = tid & 31;
    const int g = lane >> 2;       // row group 0..7
    const int t = lane & 3;        // col-pair 0..3
    const int pair   = wid >> 1;   // batch slot 0..3
    const int half16 = wid & 1;    // which 16-row half of the batch

    // ---- weight fragment tables -> smem (coalesced uint4 copy) ----
    {
        uint4* dM = (uint4*)(sw + W_FRAGM);
        uint4* dV = (uint4*)(sw + W_FRAGV);
        #pragma unroll
        for (int i = tid; i < 1024; i += THREADS) { dM[i] = g_fragM[i]; dV[i] = g_fragV[i]; }
    }

    // ---- CTA-cooperative X staging: all 4 batches, fully coalesced ----
    {
        const int base_batch = blockIdx.x * 4;
        const float4* xg = (const float4*)(X + (size_t)base_batch * 2048);
        const int nValid = nBatch - base_batch;          // >= 1
        #pragma unroll
        for (int it = 0; it < 8; ++it) {
            int i = it * THREADS + tid;      // 0..2047 float4 across 4 batches
            int b = i >> 9;                  // batch slot 0..3
            if (b < nValid) {
                float4 v = xg[i];
                int k = i & 511;
                int r = k >> 4, c = k & 15;
                uint32_t* xhb = sw + W_X + b * W_PER_BATCH;
                uint32_t* xlb = xhb + 32 * LDW;
                uint32_t h0, l0, h1, l1;
                split2(v.x, v.y, h0, l0);
                split2(v.z, v.w, h1, l1);
                xhb[r * LDW + c * 2]     = h0;
                xhb[r * LDW + c * 2 + 1] = h1;
                xlb[r * LDW + c * 2]     = l0;
                xlb[r * LDW + c * 2 + 1] = l1;
            }
        }
    }
    __syncthreads();

    const int batch = blockIdx.x * 4 + pair;
    if (batch >= nBatch) return;

    uint32_t* xh = sw + W_X + pair * W_PER_BATCH;
    uint32_t* xl = xh + 32 * LDW;
    const uint4* fragM = (const uint4*)(sw + W_FRAGM);
    const uint4* fragV = (const uint4*)(sw + W_FRAGV);

    const int rowbase = half16 * 16;      // this warp's 16 rows of the batch

    // ---- resident Xh A-fragments for rows [rowbase, rowbase+16) ----
    uint32_t XA[4][4];
    #pragma unroll
    for (int kk = 0; kk < 4; ++kk) {
        int base = (rowbase + g) * LDW + kk * 8 + t;
        XA[kk][0] = xh[base];
        XA[kk][1] = xh[base + 8 * LDW];
        XA[kk][2] = xh[base + 4];
        XA[kk][3] = xh[base + 8 * LDW + 4];
    }

    // ---- logits accumulator L[ns][4] : 16 rows x 32 cols ----
    float L[4][4];
    #pragma unroll
    for (int n = 0; n < 4; ++n)
        #pragma unroll
        for (int r = 0; r < 4; ++r) L[n][r] = 0.f;

    // ================= G1 + G2 fused over d-blocks of 16 =================
    #pragma unroll
    for (int kd = 0; kd < 4; ++kd) {
        float ya[2][4];
        #pragma unroll
        for (int j = 0; j < 2; ++j)
            #pragma unroll
            for (int r = 0; r < 4; ++r) ya[j][r] = 0.f;

        #pragma unroll
        for (int kk = 0; kk < 4; ++kk) {
            uint32_t xlf[4];
            int base = (rowbase + g) * LDW + kk * 8 + t;
            xlf[0] = xl[base];
            xlf[1] = xl[base + 8 * LDW];
            xlf[2] = xl[base + 4];
            xlf[3] = xl[base + 8 * LDW + 4];
            #pragma unroll
            for (int j = 0; j < 2; ++j) {
                uint4 mf = fragM[((2 * kd + j) * 4 + kk) * 32 + lane];
                MMA(ya[j], XA[kk], mf.x, mf.y);   // Xh * Mh
                MMA(ya[j], XA[kk], mf.z, mf.w);   // Xh * Ml
                MMA(ya[j], xlf,    mf.x, mf.y);   // Xl * Mh
            }
        }

        // Y block (16 rows x 16 d-cols) -> hi/lo A fragments in registers
        uint32_t yh[4], yl2[4];
        split2(ya[0][0], ya[0][1], yh[0], yl2[0]);
        split2(ya[0][2], ya[0][3], yh[1], yl2[1]);
        split2(ya[1][0], ya[1][1], yh[2], yl2[2]);
        split2(ya[1][2], ya[1][3], yh[3], yl2[3]);

        // G2: logits += Y_block * X^T_block  (B = X[s][d] rows as [n][k])
        #pragma unroll
        for (int ns = 0; ns < 4; ++ns) {
            int wb = (ns * 8 + g) * LDW + kd * 8 + t;
            uint32_t b0h = xh[wb], b1h = xh[wb + 4];
            uint32_t b0l = xl[wb], b1l = xl[wb + 4];
            MMA(L[ns], yh,  b0h, b1h);
            MMA(L[ns], yh,  b0l, b1l);
            MMA(L[ns], yl2, b0h, b1h);
        }
    }

    // ================= causal softmax (registers + quad shuffles) =================
    #pragma unroll
    for (int hh = 0; hh < 2; ++hh) {
        int r = rowbase + g + hh * 8;
        float vmax = -3.0e38f;
        #pragma unroll
        for (int n = 0; n < 4; ++n) {
            int c0 = n * 8 + t * 2;
            float v0 = L[n][hh * 2 + 0], v1 = L[n][hh * 2 + 1];
            if (c0     <= r && v0 > vmax) vmax = v0;
            if (c0 + 1 <= r && v1 > vmax) vmax = v1;
        }
        vmax = fmaxf(vmax, __shfl_xor_sync(0xffffffffu, vmax, 1));
        vmax = fmaxf(vmax, __shfl_xor_sync(0xffffffffu, vmax, 2));
        float sum = 0.f;
        #pragma unroll
        for (int n = 0; n < 4; ++n) {
            int c0 = n * 8 + t * 2;
            float e0 = (c0     <= r) ? __expf(L[n][hh * 2 + 0] - vmax) : 0.f;
            float e1 = (c0 + 1 <= r) ? __expf(L[n][hh * 2 + 1] - vmax) : 0.f;
            L[n][hh * 2 + 0] = e0;
            L[n][hh * 2 + 1] = e1;
            sum += e0 + e1;
        }
        sum += __shfl_xor_sync(0xffffffffu, sum, 1);
        sum += __shfl_xor_sync(0xffffffffu, sum, 2);
        float inv = 1.0f / sum;
        #pragma unroll
        for (int n = 0; n < 4; ++n) {
            L[n][hh * 2 + 0] *= inv;
            L[n][hh * 2 + 1] *= inv;
        }
    }

    // P A-fragments (fp16 hi only): PF[ks] covers 16 rows x s-cols ks*16..
    uint32_t PF[2][4];
    #pragma unroll
    for (int ks = 0; ks < 2; ++ks) {
        PF[ks][0] = pack2f(L[2 * ks][0],     L[2 * ks][1]);
        PF[ks][1] = pack2f(L[2 * ks][2],     L[2 * ks][3]);
        PF[ks][2] = pack2f(L[2 * ks + 1][0], L[2 * ks + 1][1]);
        PF[ks][3] = pack2f(L[2 * ks + 1][2], L[2 * ks + 1][3]);
    }

    // ================= G3: Z = P * X  (B col-major frags via u16 gathers) =====
    uint32_t ZF[4][4];
    const __half* xhh = (const __half*)xh;
    const __half* xlh = (const __half*)xl;
    #pragma unroll
    for (int nd = 0; nd < 8; ++nd) {
        float za[4] = {0.f, 0.f, 0.f, 0.f};
        #pragma unroll
        for (int ks = 0; ks < 2; ++ks) {
            int r0 = ks * 16 + t * 2;           // k rows (s)
            int c  = nd * 8 + g;                // n col (d)
            uint32_t bh0 = packh(xhh[r0 * 72 + c],       xhh[(r0 + 1) * 72 + c]);
            uint32_t bh1 = packh(xhh[(r0 + 8) * 72 + c], xhh[(r0 + 9) * 72 + c]);
            uint32_t bl0 = packh(xlh[r0 * 72 + c],       xlh[(r0 + 1) * 72 + c]);
            uint32_t bl1 = packh(xlh[(r0 + 8) * 72 + c], xlh[(r0 + 9) * 72 + c]);
            MMA(za, PF[ks], bh0, bh1);
            MMA(za, PF[ks], bl0, bl1);
        }
        int kk = nd >> 1;
        if ((nd & 1) == 0) {
            ZF[kk][0] = pack2f(za[0], za[1]);
            ZF[kk][1] = pack2f(za[2], za[3]);
        } else {
            ZF[kk][2] = pack2f(za[0], za[1]);
            ZF[kk][3] = pack2f(za[2], za[3]);
        }
    }

    // ================= G4: out = Z * Wv' (+ direct stores) =================
    float* outp = Out + (size_t)batch * 2048;
    #pragma unroll
    for (int nh = 0; nh < 8; ++nh) {
        float oa[4] = {0.f, 0.f, 0.f, 0.f};
        #pragma unroll
        for (int kk = 0; kk < 4; ++kk) {
            uint4 wf = fragV[(nh * 4 + kk) * 32 + lane];
            MMA(oa, ZF[kk], wf.x, wf.y);
            MMA(oa, ZF[kk], wf.z, wf.w);
        }
        int r = rowbase + g;
        *(float2*)(outp + r * 64 + nh * 8 + t * 2)       = make_float2(oa[0], oa[1]);
        *(float2*)(outp + (r + 8) * 64 + nh * 8 + t * 2) = make_float2(oa[2], oa[3]);
    }
}

extern "C" void kernel_launch(void* const* d_in, const int* in_sizes, int n_in,
                              void* d_out, int out_size)
{
    const float* X  = (const float*)d_in[0];
    const float* Wk = (const float*)d_in[1];
    const float* Wq = (const float*)d_in[2];
    const float* Wv = (const float*)d_in[3];
    float* Out = (float*)d_out;

    const int nBatch = in_sizes[0] / 2048;

    cudaFuncSetAttribute(attn_kernel,
                         cudaFuncAttributeMaxDynamicSharedMemorySize, SMEM_BYTES);

    prep_weights<<<8, 256>>>(Wk, Wq, Wv);

    int grid = (nBatch + 3) / 4;
    attn_kernel<<<grid, THREADS, SMEM_BYTES>>>(X, Out, nBatch);
}

// round 8
// speedup vs baseline: 1.1135x; 1.1135x over previous
#include <cuda_runtime.h>
#include <cuda_fp16.h>
#include <cstdint>

// ============================================================================
// Fused attention via warp-level mma.sync + ldmatrix (sm_100 base target).
//   out = softmax_causal( X * (8 Wq Wk^T) * X^T ) * X * Wv
// B=16384 batches, T=32, D=H=64, fp32 I/O.
// R8: two warps per batch; ALL X fragment loads via ldmatrix.x4 (incl. .trans
//     for G3's implicit transpose); G3/G4 use hi-only fp16 (no lo split);
//     G1/G2 keep the 3-way split to protect logits. 3 CTAs/SM target.
// ============================================================================

#define THREADS 256          // 8 warps = 4 batches per CTA
#define LDW     36           // u32 words per X smem row (72 halves, 144 B)

// smem word offsets
#define W_FRAGM 0                       // 1024 uint4 = 4096 words
#define W_FRAGV 4096                    // 1024 uint2 = 2048 words
#define W_X     6144                    // per batch: Xh 32*36 + Xl 32*36 words
#define W_PER_BATCH (2 * 32 * LDW)
#define SMEM_WORDS (W_X + 4 * W_PER_BATCH)
#define SMEM_BYTES (SMEM_WORDS * 4)     // 61440 B

// ---- weight fragment tables ----
__device__ uint4 g_fragM[1024];   // M8' B-frags: {bh0,bh1,bl0,bl1}
__device__ uint2 g_fragV[1024];   // Wv' B-frags: {bh0,bh1} (hi only)

__device__ __forceinline__ uint32_t pack2f(float a, float b) {
    __half2 hh = __floats2half2_rn(a, b);
    return *(uint32_t*)&hh;
}

__global__ void prep_weights(const float* __restrict__ Wk, const float* __restrict__ Wq,
                             const float* __restrict__ Wv) {
    int e = blockIdx.x * blockDim.x + threadIdx.x;
    if (e >= 2048) return;
    int table = e >> 10;
    int idx   = e & 1023;
    int frag  = idx >> 5;          // jt*4 + kk
    int lane  = idx & 31;
    int jt = frag >> 2, kk = frag & 3;
    int g = lane >> 2, t = lane & 3;
    int n  = jt * 8 + g;
    int k0 = kk * 16 + 2 * t;

    float v[4];
    int ks[4] = { k0, k0 + 1, k0 + 8, k0 + 9 };
    if (table == 0) {
        #pragma unroll
        for (int i = 0; i < 4; ++i) {
            float s = 0.f;
            const float* qa = Wq + ks[i] * 64;
            const float* kb = Wk + n * 64;
            #pragma unroll
            for (int h = 0; h < 64; ++h) s = fmaf(qa[h], kb[h], s);
            v[i] = 8.0f * s;
        }
        float hi[4], lo[4];
        #pragma unroll
        for (int i = 0; i < 4; ++i) {
            __half h = __float2half_rn(v[i]);
            hi[i] = __half2float(h);
            lo[i] = v[i] - hi[i];
        }
        uint4 out;
        out.x = pack2f(hi[0], hi[1]);
        out.y = pack2f(hi[2], hi[3]);
        out.z = pack2f(lo[0], lo[1]);
        out.w = pack2f(lo[2], lo[3]);
        g_fragM[idx] = out;
    } else {
        #pragma unroll
        for (int i = 0; i < 4; ++i) v[i] = Wv[ks[i] * 64 + n];
        uint2 out;
        out.x = pack2f(v[0], v[1]);    // rn-rounded fp16 hi
        out.y = pack2f(v[2], v[3]);
        g_fragV[idx] = out;
    }
}

// ---- helpers ----
#define MMA(d, a, b0, b1) asm volatile( \
    "mma.sync.aligned.m16n8k16.row.col.f32.f16.f16.f32 " \
    "{%0,%1,%2,%3}, {%4,%5,%6,%7}, {%8,%9}, {%0,%1,%2,%3};" \
    : "+f"((d)[0]), "+f"((d)[1]), "+f"((d)[2]), "+f"((d)[3]) \
    : "r"((a)[0]), "r"((a)[1]), "r"((a)[2]), "r"((a)[3]), \
      "r"(b0), "r"(b1))

#define LDSM4(r, addr) asm volatile( \
    "ldmatrix.sync.aligned.m8n8.x4.shared.b16 {%0,%1,%2,%3}, [%4];" \
    : "=r"((r)[0]), "=r"((r)[1]), "=r"((r)[2]), "=r"((r)[3]) : "r"(addr))

#define LDSM4T(r, addr) asm volatile( \
    "ldmatrix.sync.aligned.m8n8.x4.trans.shared.b16 {%0,%1,%2,%3}, [%4];" \
    : "=r"((r)[0]), "=r"((r)[1]), "=r"((r)[2]), "=r"((r)[3]) : "r"(addr))

__device__ __forceinline__ uint32_t smem_u32(const void* p) {
    uint32_t a;
    asm("{ .reg .u64 t; cvta.to.shared.u64 t, %1; cvt.u32.u64 %0, t; }" : "=r"(a) : "l"(p));
    return a;
}

__device__ __forceinline__ void split2(float a, float b, uint32_t& h, uint32_t& l) {
    __half2 hh = __floats2half2_rn(a, b);
    float2 hf = __half22float2(hh);
    __half2 ll = __floats2half2_rn(a - hf.x, b - hf.y);
    h = *(uint32_t*)&hh;
    l = *(uint32_t*)&ll;
}

__global__ void __launch_bounds__(THREADS, 3)
attn_kernel(const float* __restrict__ X, float* __restrict__ Out, int nBatch)
{
    extern __shared__ uint32_t sw[];
    const int tid  = threadIdx.x;
    const int wid  = tid >> 5;
    const int lane = tid & 31;
    const int g = lane >> 2;       // row group 0..7
    const int t = lane & 3;        // col-pair 0..3
    const int pair   = wid >> 1;   // batch slot 0..3
    const int half16 = wid & 1;    // which 16-row half of the batch

    // ---- weight fragment tables -> smem (coalesced copies) ----
    {
        uint4* dM = (uint4*)(sw + W_FRAGM);
        uint2* dV = (uint2*)(sw + W_FRAGV);
        #pragma unroll
        for (int i = tid; i < 1024; i += THREADS) { dM[i] = g_fragM[i]; dV[i] = g_fragV[i]; }
    }

    // ---- CTA-cooperative X staging: all 4 batches, fully coalesced ----
    {
        const int base_batch = blockIdx.x * 4;
        const float4* xg = (const float4*)(X + (size_t)base_batch * 2048);
        const int nValid = nBatch - base_batch;          // >= 1
        #pragma unroll
        for (int it = 0; it < 8; ++it) {
            int i = it * THREADS + tid;      // 0..2047 float4 across 4 batches
            int b = i >> 9;                  // batch slot 0..3
            if (b < nValid) {
                float4 v = xg[i];
                int k = i & 511;
                int r = k >> 4, c = k & 15;
                uint32_t* xhb = sw + W_X + b * W_PER_BATCH;
                uint32_t* xlb = xhb + 32 * LDW;
                uint32_t h0, l0, h1, l1;
                split2(v.x, v.y, h0, l0);
                split2(v.z, v.w, h1, l1);
                xhb[r * LDW + c * 2]     = h0;
                xhb[r * LDW + c * 2 + 1] = h1;
                xlb[r * LDW + c * 2]     = l0;
                xlb[r * LDW + c * 2 + 1] = l1;
            }
        }
    }
    __syncthreads();

    const int batch = blockIdx.x * 4 + pair;
    if (batch >= nBatch) return;

    const uint32_t xh_b = smem_u32(sw) + (W_X + pair * W_PER_BATCH) * 4;
    const uint32_t xl_b = xh_b + 32 * LDW * 4;
    const uint4* fragM = (const uint4*)(sw + W_FRAGM);
    const uint2* fragV = (const uint2*)(sw + W_FRAGV);

    const int rowbase = half16 * 16;      // this warp's 16 rows of the batch
    const int lr = lane & 7;
    // ldmatrix per-lane address offsets (bytes) for the two tile patterns:
    //  patA (A-frags & G3 trans-B): m0/m1 split rows, m2/m3 split cols
    //  patB (G2 B-frags):           m0/m1 split cols, m2/m3 split rows
    const uint32_t offA = (uint32_t)((((lane >> 3) & 1) * 8 + lr) * 144 + ((lane >> 4) & 1) * 16);
    const uint32_t offB = (uint32_t)((((lane >> 4) & 1) * 8 + lr) * 144 + ((lane >> 3) & 1) * 16);

    // ---- resident Xh A-fragments for rows [rowbase, rowbase+16) ----
    uint32_t XA[4][4];
    #pragma unroll
    for (int kk = 0; kk < 4; ++kk)
        LDSM4(XA[kk], xh_b + (uint32_t)rowbase * 144 + offA + kk * 32);

    // ---- logits accumulator L[ns][4] : 16 rows x 32 cols ----
    float L[4][4];
    #pragma unroll
    for (int n = 0; n < 4; ++n)
        #pragma unroll
        for (int r = 0; r < 4; ++r) L[n][r] = 0.f;

    // ================= G1 + G2 fused over d-blocks of 16 =================
    #pragma unroll
    for (int kd = 0; kd < 4; ++kd) {
        float ya[2][4];
        #pragma unroll
        for (int j = 0; j < 2; ++j)
            #pragma unroll
            for (int r = 0; r < 4; ++r) ya[j][r] = 0.f;

        #pragma unroll
        for (int kk = 0; kk < 4; ++kk) {
            uint32_t xlf[4];
            LDSM4(xlf, xl_b + (uint32_t)rowbase * 144 + offA + kk * 32);
            #pragma unroll
            for (int j = 0; j < 2; ++j) {
                uint4 mf = fragM[((2 * kd + j) * 4 + kk) * 32 + lane];
                MMA(ya[j], XA[kk], mf.x, mf.y);   // Xh * Mh
                MMA(ya[j], XA[kk], mf.z, mf.w);   // Xh * Ml
                MMA(ya[j], xlf,    mf.x, mf.y);   // Xl * Mh
            }
        }

        // Y block (16 rows x 16 d-cols) -> hi/lo A fragments in registers
        uint32_t yh[4], yl2[4];
        split2(ya[0][0], ya[0][1], yh[0], yl2[0]);
        split2(ya[0][2], ya[0][3], yh[1], yl2[1]);
        split2(ya[1][0], ya[1][1], yh[2], yl2[2]);
        split2(ya[1][2], ya[1][3], yh[3], yl2[3]);

        // G2: logits += Y_block * X^T_block  (B = X rows as [n=s][k=d])
        #pragma unroll
        for (int p = 0; p < 2; ++p) {       // ns pair (2p, 2p+1)
            uint32_t bh[4], bl[4];
            LDSM4(bh, xh_b + (uint32_t)(p * 16) * 144 + offB + kd * 32);
            LDSM4(bl, xl_b + (uint32_t)(p * 16) * 144 + offB + kd * 32);
            MMA(L[2 * p],     yh,  bh[0], bh[1]);
            MMA(L[2 * p],     yh,  bl[0], bl[1]);
            MMA(L[2 * p],     yl2, bh[0], bh[1]);
            MMA(L[2 * p + 1], yh,  bh[2], bh[3]);
            MMA(L[2 * p + 1], yh,  bl[2], bl[3]);
            MMA(L[2 * p + 1], yl2, bh[2], bh[3]);
        }
    }

    // ================= causal softmax (registers + quad shuffles) =================
    #pragma unroll
    for (int hh = 0; hh < 2; ++hh) {
        int r = rowbase + g + hh * 8;
        float vmax = -3.0e38f;
        #pragma unroll
        for (int n = 0; n < 4; ++n) {
            int c0 = n * 8 + t * 2;
            float v0 = L[n][hh * 2 + 0], v1 = L[n][hh * 2 + 1];
            if (c0     <= r && v0 > vmax) vmax = v0;
            if (c0 + 1 <= r && v1 > vmax) vmax = v1;
        }
        vmax = fmaxf(vmax, __shfl_xor_sync(0xffffffffu, vmax, 1));
        vmax = fmaxf(vmax, __shfl_xor_sync(0xffffffffu, vmax, 2));
        float sum = 0.f;
        #pragma unroll
        for (int n = 0; n < 4; ++n) {
            int c0 = n * 8 + t * 2;
            float e0 = (c0     <= r) ? __expf(L[n][hh * 2 + 0] - vmax) : 0.f;
            float e1 = (c0 + 1 <= r) ? __expf(L[n][hh * 2 + 1] - vmax) : 0.f;
            L[n][hh * 2 + 0] = e0;
            L[n][hh * 2 + 1] = e1;
            sum += e0 + e1;
        }
        sum += __shfl_xor_sync(0xffffffffu, sum, 1);
        sum += __shfl_xor_sync(0xffffffffu, sum, 2);
        float inv = 1.0f / sum;
        #pragma unroll
        for (int n = 0; n < 4; ++n) {
            L[n][hh * 2 + 0] *= inv;
            L[n][hh * 2 + 1] *= inv;
        }
    }

    // P A-fragments (fp16 hi only): PF[ks] covers 16 rows x s-cols ks*16..
    uint32_t PF[2][4];
    #pragma unroll
    for (int ks = 0; ks < 2; ++ks) {
        PF[ks][0] = pack2f(L[2 * ks][0],     L[2 * ks][1]);
        PF[ks][1] = pack2f(L[2 * ks][2],     L[2 * ks][3]);
        PF[ks][2] = pack2f(L[2 * ks + 1][0], L[2 * ks + 1][1]);
        PF[ks][3] = pack2f(L[2 * ks + 1][2], L[2 * ks + 1][3]);
    }

    // ================= G3: Z = P * X   (B via ldmatrix.trans; hi only) ========
    uint32_t ZF[4][4];
    #pragma unroll
    for (int q = 0; q < 4; ++q) {          // nd pair (2q, 2q+1)
        float za[2][4];
        #pragma unroll
        for (int j = 0; j < 2; ++j)
            #pragma unroll
            for (int r = 0; r < 4; ++r) za[j][r] = 0.f;
        #pragma unroll
        for (int ks = 0; ks < 2; ++ks) {
            uint32_t bf[4];
            LDSM4T(bf, xh_b + (uint32_t)(ks * 16) * 144 + offA + q * 32);
            MMA(za[0], PF[ks], bf[0], bf[1]);
            MMA(za[1], PF[ks], bf[2], bf[3]);
        }
        ZF[q][0] = pack2f(za[0][0], za[0][1]);
        ZF[q][1] = pack2f(za[0][2], za[0][3]);
        ZF[q][2] = pack2f(za[1][0], za[1][1]);
        ZF[q][3] = pack2f(za[1][2], za[1][3]);
    }

    // ================= G4: out = Z * Wv' (hi only, direct stores) =============
    float* outp = Out + (size_t)batch * 2048;
    #pragma unroll
    for (int nh = 0; nh < 8; ++nh) {
        float oa[4] = {0.f, 0.f, 0.f, 0.f};
        #pragma unroll
        for (int kk = 0; kk < 4; ++kk) {
            uint2 wf = fragV[(nh * 4 + kk) * 32 + lane];
            MMA(oa, ZF[kk], wf.x, wf.y);
        }
        int r = rowbase + g;
        *(float2*)(outp + r * 64 + nh * 8 + t * 2)       = make_float2(oa[0], oa[1]);
        *(float2*)(outp + (r + 8) * 64 + nh * 8 + t * 2) = make_float2(oa[2], oa[3]);
    }
}

extern "C" void kernel_launch(void* const* d_in, const int* in_sizes, int n_in,
                              void* d_out, int out_size)
{
    const float* X  = (const float*)d_in[0];
    const float* Wk = (const float*)d_in[1];
    const float* Wq = (const float*)d_in[2];
    const float* Wv = (const float*)d_in[3];
    float* Out = (float*)d_out;

    const int nBatch = in_sizes[0] / 2048;

    cudaFuncSetAttribute(attn_kernel,
                         cudaFuncAttributeMaxDynamicSharedMemorySize, SMEM_BYTES);

    prep_weights<<<8, 256>>>(Wk, Wq, Wv);

    int grid = (nBatch + 3) / 4;
    attn_kernel<<<grid, THREADS, SMEM_BYTES>>>(X, Out, nBatch);
}

// round 9
// speedup vs baseline: 1.1937x; 1.0720x over previous
#include <cuda_runtime.h>
#include <cuda_fp16.h>
#include <cstdint>

// ============================================================================
// Fused attention via warp-level mma.sync + ldmatrix (sm_100 base target).
//   out = softmax_causal( X * (8 Wq Wk^T) * X^T ) * X * Wv
// B=16384 batches, T=32, D=H=64, fp32 I/O.
// R9: ONE warp per batch (32 rows) to amortize all B-operand smem traffic;
//     ldmatrix.x4 for every X fragment (incl. .trans in G3); hi-only fp16 in
//     G3/G4; 3-way fp16 split in G1/G2. fragV packed for LDS.128.
// ============================================================================

#define THREADS 256          // 8 warps = 8 batches per CTA
#define LDW     36           // u32 words per X smem row (72 halves, 144 B)

// smem word offsets
#define W_FRAGM 0                       // 1024 uint4 = 4096 words
#define W_FRAGV 4096                    // 512 uint4 = 2048 words
#define W_X     6144                    // per batch: Xh 32*36 + Xl 32*36 words
#define W_PER_BATCH (2 * 32 * LDW)
#define SMEM_WORDS (W_X + 8 * W_PER_BATCH)
#define SMEM_BYTES (SMEM_WORDS * 4)     // 98304 B

// ---- weight fragment tables ----
__device__ uint4 g_fragM[1024];   // M8' B-frags: {bh0,bh1,bl0,bl1}, idx=((jt*4+kk)*32+lane)
__device__ uint4 g_fragV4[512];   // Wv' hi B-frags, kk-pairs: {kk=2e, kk=2e+1}

__device__ __forceinline__ uint32_t pack2f(float a, float b) {
    __half2 hh = __floats2half2_rn(a, b);
    return *(uint32_t*)&hh;
}

__global__ void prep_weights(const float* __restrict__ Wk, const float* __restrict__ Wq,
                             const float* __restrict__ Wv) {
    int e = blockIdx.x * blockDim.x + threadIdx.x;
    if (e < 1024) {
        // fragM: frag (jt,kk), lane
        int frag  = e >> 5;
        int lane  = e & 31;
        int jt = frag >> 2, kk = frag & 3;
        int g = lane >> 2, t = lane & 3;
        int n  = jt * 8 + g;
        int k0 = kk * 16 + 2 * t;
        int ks[4] = { k0, k0 + 1, k0 + 8, k0 + 9 };
        float v[4], hi[4], lo[4];
        #pragma unroll
        for (int i = 0; i < 4; ++i) {
            float s = 0.f;
            const float* qa = Wq + ks[i] * 64;
            const float* kb = Wk + n * 64;
            #pragma unroll
            for (int h = 0; h < 64; ++h) s = fmaf(qa[h], kb[h], s);
            v[i] = 8.0f * s;
            __half hh = __float2half_rn(v[i]);
            hi[i] = __half2float(hh);
            lo[i] = v[i] - hi[i];
        }
        uint4 out;
        out.x = pack2f(hi[0], hi[1]);
        out.y = pack2f(hi[2], hi[3]);
        out.z = pack2f(lo[0], lo[1]);
        out.w = pack2f(lo[2], lo[3]);
        g_fragM[e] = out;
    } else if (e < 1536) {
        // fragV4: pairidx = nh*2 + ep (ep selects kk pair {2ep, 2ep+1}), lane
        int idx2 = e - 1024;
        int pairidx = idx2 >> 5;
        int lane = idx2 & 31;
        int nh = pairidx >> 1, ep = pairidx & 1;
        int g = lane >> 2, t = lane & 3;
        int n = nh * 8 + g;
        uint4 out;
        uint32_t* w = (uint32_t*)&out;
        #pragma unroll
        for (int half = 0; half < 2; ++half) {
            int kk = 2 * ep + half;
            int k0 = kk * 16 + 2 * t;
            float v0 = Wv[k0 * 64 + n],       v1 = Wv[(k0 + 1) * 64 + n];
            float v2 = Wv[(k0 + 8) * 64 + n], v3 = Wv[(k0 + 9) * 64 + n];
            w[half * 2 + 0] = pack2f(v0, v1);
            w[half * 2 + 1] = pack2f(v2, v3);
        }
        g_fragV4[pairidx * 32 + lane] = out;
    }
}

// ---- helpers ----
#define MMA(d, a, b0, b1) asm volatile( \
    "mma.sync.aligned.m16n8k16.row.col.f32.f16.f16.f32 " \
    "{%0,%1,%2,%3}, {%4,%5,%6,%7}, {%8,%9}, {%0,%1,%2,%3};" \
    : "+f"((d)[0]), "+f"((d)[1]), "+f"((d)[2]), "+f"((d)[3]) \
    : "r"((a)[0]), "r"((a)[1]), "r"((a)[2]), "r"((a)[3]), \
      "r"(b0), "r"(b1))

#define LDSM4(r, addr) asm volatile( \
    "ldmatrix.sync.aligned.m8n8.x4.shared.b16 {%0,%1,%2,%3}, [%4];" \
    : "=r"((r)[0]), "=r"((r)[1]), "=r"((r)[2]), "=r"((r)[3]) : "r"(addr))

#define LDSM4T(r, addr) asm volatile( \
    "ldmatrix.sync.aligned.m8n8.x4.trans.shared.b16 {%0,%1,%2,%3}, [%4];" \
    : "=r"((r)[0]), "=r"((r)[1]), "=r"((r)[2]), "=r"((r)[3]) : "r"(addr))

__device__ __forceinline__ uint32_t smem_u32(const void* p) {
    uint32_t a;
    asm("{ .reg .u64 t; cvta.to.shared.u64 t, %1; cvt.u32.u64 %0, t; }" : "=r"(a) : "l"(p));
    return a;
}

__device__ __forceinline__ void split2(float a, float b, uint32_t& h, uint32_t& l) {
    __half2 hh = __floats2half2_rn(a, b);
    float2 hf = __half22float2(hh);
    __half2 ll = __floats2half2_rn(a - hf.x, b - hf.y);
    h = *(uint32_t*)&hh;
    l = *(uint32_t*)&ll;
}

__global__ void __launch_bounds__(THREADS, 2)
attn_kernel(const float* __restrict__ X, float* __restrict__ Out, int nBatch)
{
    extern __shared__ uint32_t sw[];
    const int tid  = threadIdx.x;
    const int wid  = tid >> 5;
    const int lane = tid & 31;
    const int g = lane >> 2;       // row group 0..7
    const int t = lane & 3;        // col-pair 0..3

    // ---- weight fragment tables -> smem (coalesced copies) ----
    {
        uint4* dM = (uint4*)(sw + W_FRAGM);
        uint4* dV = (uint4*)(sw + W_FRAGV);
        #pragma unroll
        for (int i = tid; i < 1024; i += THREADS) dM[i] = g_fragM[i];
        #pragma unroll
        for (int i = tid; i < 512; i += THREADS) dV[i] = g_fragV4[i];
    }

    // ---- CTA-cooperative X staging: all 8 batches, fully coalesced ----
    {
        const int base_batch = blockIdx.x * 8;
        const float4* xg = (const float4*)(X + (size_t)base_batch * 2048);
        const int nValid = nBatch - base_batch;          // >= 1
        #pragma unroll
        for (int it = 0; it < 16; ++it) {
            int i = it * THREADS + tid;      // 0..4095 float4 across 8 batches
            int b = i >> 9;                  // batch slot 0..7
            if (b < nValid) {
                float4 v = xg[i];
                int k = i & 511;
                int r = k >> 4, c = k & 15;
                uint32_t* xhb = sw + W_X + b * W_PER_BATCH;
                uint32_t* xlb = xhb + 32 * LDW;
                uint32_t h0, l0, h1, l1;
                split2(v.x, v.y, h0, l0);
                split2(v.z, v.w, h1, l1);
                xhb[r * LDW + c * 2]     = h0;
                xhb[r * LDW + c * 2 + 1] = h1;
                xlb[r * LDW + c * 2]     = l0;
                xlb[r * LDW + c * 2 + 1] = l1;
            }
        }
    }
    __syncthreads();

    const int batch = blockIdx.x * 8 + wid;
    if (batch >= nBatch) return;

    const uint32_t xh_b = smem_u32(sw) + (W_X + wid * W_PER_BATCH) * 4;
    const uint32_t xl_b = xh_b + 32 * LDW * 4;
    const uint4* fragM = (const uint4*)(sw + W_FRAGM);
    const uint4* fragV = (const uint4*)(sw + W_FRAGV);

    const int lr = lane & 7;
    // ldmatrix per-lane address offsets (bytes):
    //  patA (A-frags & G3 trans-B): m0/m1 split rows, m2/m3 split cols
    //  patB (G2 B-frags):           m0/m1 split cols, m2/m3 split rows
    const uint32_t offA = (uint32_t)((((lane >> 3) & 1) * 8 + lr) * 144 + ((lane >> 4) & 1) * 16);
    const uint32_t offB = (uint32_t)((((lane >> 4) & 1) * 8 + lr) * 144 + ((lane >> 3) & 1) * 16);

    // ---- resident Xh A-fragments, both 16-row tiles (m=0: rows 0-15, m=1: 16-31) ----
    uint32_t XA[2][4][4];
    #pragma unroll
    for (int m = 0; m < 2; ++m)
        #pragma unroll
        for (int kk = 0; kk < 4; ++kk)
            LDSM4(XA[m][kk], xh_b + (uint32_t)(m * 16) * 144 + offA + kk * 32);

    // ---- logits accumulator L[m][ns][4] : 32 rows x 32 cols ----
    float L[2][4][4];
    #pragma unroll
    for (int m = 0; m < 2; ++m)
        #pragma unroll
        for (int n = 0; n < 4; ++n)
            #pragma unroll
            for (int r = 0; r < 4; ++r) L[m][n][r] = 0.f;

    // ================= G1 + G2 fused over d-blocks of 16 =================
    #pragma unroll
    for (int kd = 0; kd < 4; ++kd) {
        float ya[2][2][4];
        #pragma unroll
        for (int m = 0; m < 2; ++m)
            #pragma unroll
            for (int j = 0; j < 2; ++j)
                #pragma unroll
                for (int r = 0; r < 4; ++r) ya[m][j][r] = 0.f;

        #pragma unroll
        for (int kk = 0; kk < 4; ++kk) {
            #pragma unroll
            for (int m = 0; m < 2; ++m) {
                uint32_t xlf[4];
                LDSM4(xlf, xl_b + (uint32_t)(m * 16) * 144 + offA + kk * 32);
                #pragma unroll
                for (int j = 0; j < 2; ++j) {
                    uint4 mf = fragM[((2 * kd + j) * 4 + kk) * 32 + lane];
                    MMA(ya[m][j], XA[m][kk], mf.x, mf.y);   // Xh * Mh
                    MMA(ya[m][j], XA[m][kk], mf.z, mf.w);   // Xh * Ml
                    MMA(ya[m][j], xlf,       mf.x, mf.y);   // Xl * Mh
                }
            }
        }

        // Y blocks -> hi/lo A fragments in registers
        uint32_t yh[2][4], yl2[2][4];
        #pragma unroll
        for (int m = 0; m < 2; ++m) {
            split2(ya[m][0][0], ya[m][0][1], yh[m][0], yl2[m][0]);
            split2(ya[m][0][2], ya[m][0][3], yh[m][1], yl2[m][1]);
            split2(ya[m][1][0], ya[m][1][1], yh[m][2], yl2[m][2]);
            split2(ya[m][1][2], ya[m][1][3], yh[m][3], yl2[m][3]);
        }

        // G2: logits += Y_block * X^T_block  (B = X rows as [n=s][k=d])
        #pragma unroll
        for (int p = 0; p < 2; ++p) {       // ns pair (2p, 2p+1)
            uint32_t bh[4], bl[4];
            LDSM4(bh, xh_b + (uint32_t)(p * 16) * 144 + offB + kd * 32);
            LDSM4(bl, xl_b + (uint32_t)(p * 16) * 144 + offB + kd * 32);
            #pragma unroll
            for (int m = 0; m < 2; ++m) {
                MMA(L[m][2 * p],     yh[m],  bh[0], bh[1]);
                MMA(L[m][2 * p],     yh[m],  bl[0], bl[1]);
                MMA(L[m][2 * p],     yl2[m], bh[0], bh[1]);
                MMA(L[m][2 * p + 1], yh[m],  bh[2], bh[3]);
                MMA(L[m][2 * p + 1], yh[m],  bl[2], bl[3]);
                MMA(L[m][2 * p + 1], yl2[m], bh[2], bh[3]);
            }
        }
    }

    // ================= causal softmax (registers + quad shuffles) =================
    #pragma unroll
    for (int m = 0; m < 2; ++m)
        #pragma unroll
        for (int hh = 0; hh < 2; ++hh) {
            int r = m * 16 + g + hh * 8;
            float vmax = -3.0e38f;
            #pragma unroll
            for (int n = 0; n < 4; ++n) {
                int c0 = n * 8 + t * 2;
                float v0 = L[m][n][hh * 2 + 0], v1 = L[m][n][hh * 2 + 1];
                if (c0     <= r && v0 > vmax) vmax = v0;
                if (c0 + 1 <= r && v1 > vmax) vmax = v1;
            }
            vmax = fmaxf(vmax, __shfl_xor_sync(0xffffffffu, vmax, 1));
            vmax = fmaxf(vmax, __shfl_xor_sync(0xffffffffu, vmax, 2));
            float sum = 0.f;
            #pragma unroll
            for (int n = 0; n < 4; ++n) {
                int c0 = n * 8 + t * 2;
                float e0 = (c0     <= r) ? __expf(L[m][n][hh * 2 + 0] - vmax) : 0.f;
                float e1 = (c0 + 1 <= r) ? __expf(L[m][n][hh * 2 + 1] - vmax) : 0.f;
                L[m][n][hh * 2 + 0] = e0;
                L[m][n][hh * 2 + 1] = e1;
                sum += e0 + e1;
            }
            sum += __shfl_xor_sync(0xffffffffu, sum, 1);
            sum += __shfl_xor_sync(0xffffffffu, sum, 2);
            float inv = 1.0f / sum;
            #pragma unroll
            for (int n = 0; n < 4; ++n) {
                L[m][n][hh * 2 + 0] *= inv;
                L[m][n][hh * 2 + 1] *= inv;
            }
        }

    // P A-fragments (fp16 hi only): PF[m][ks] covers rows m*16.. x s-cols ks*16..
    uint32_t PF[2][2][4];
    #pragma unroll
    for (int m = 0; m < 2; ++m)
        #pragma unroll
        for (int ks = 0; ks < 2; ++ks) {
            PF[m][ks][0] = pack2f(L[m][2 * ks][0],     L[m][2 * ks][1]);
            PF[m][ks][1] = pack2f(L[m][2 * ks][2],     L[m][2 * ks][3]);
            PF[m][ks][2] = pack2f(L[m][2 * ks + 1][0], L[m][2 * ks + 1][1]);
            PF[m][ks][3] = pack2f(L[m][2 * ks + 1][2], L[m][2 * ks + 1][3]);
        }

    // ================= G3: Z = P * X   (B via ldmatrix.trans; hi only) ========
    uint32_t ZF[2][4][4];
    #pragma unroll
    for (int q = 0; q < 4; ++q) {          // nd pair (2q, 2q+1)
        float za[2][2][4];
        #pragma unroll
        for (int m = 0; m < 2; ++m)
            #pragma unroll
            for (int j = 0; j < 2; ++j)
                #pragma unroll
                for (int r = 0; r < 4; ++r) za[m][j][r] = 0.f;
        #pragma unroll
        for (int ks = 0; ks < 2; ++ks) {
            uint32_t bf[4];
            LDSM4T(bf, xh_b + (uint32_t)(ks * 16) * 144 + offA + q * 32);
            #pragma unroll
            for (int m = 0; m < 2; ++m) {
                MMA(za[m][0], PF[m][ks], bf[0], bf[1]);
                MMA(za[m][1], PF[m][ks], bf[2], bf[3]);
            }
        }
        #pragma unroll
        for (int m = 0; m < 2; ++m) {
            ZF[m][q][0] = pack2f(za[m][0][0], za[m][0][1]);
            ZF[m][q][1] = pack2f(za[m][0][2], za[m][0][3]);
            ZF[m][q][2] = pack2f(za[m][1][0], za[m][1][1]);
            ZF[m][q][3] = pack2f(za[m][1][2], za[m][1][3]);
        }
    }

    // ================= G4: out = Z * Wv' (hi only, direct stores) =============
    float* outp = Out + (size_t)batch * 2048;
    #pragma unroll
    for (int nh = 0; nh < 8; ++nh) {
        float oa[2][4];
        #pragma unroll
        for (int m = 0; m < 2; ++m)
            #pragma unroll
            for (int r = 0; r < 4; ++r) oa[m][r] = 0.f;
        #pragma unroll
        for (int e = 0; e < 2; ++e) {       // kk pair {2e, 2e+1}
            uint4 wf = fragV[(nh * 2 + e) * 32 + lane];
            #pragma unroll
            for (int m = 0; m < 2; ++m) {
                MMA(oa[m], ZF[m][2 * e],     wf.x, wf.y);
                MMA(oa[m], ZF[m][2 * e + 1], wf.z, wf.w);
            }
        }
        #pragma unroll
        for (int m = 0; m < 2; ++m) {
            int r = m * 16 + g;
            *(float2*)(outp + r * 64 + nh * 8 + t * 2)       = make_float2(oa[m][0], oa[m][1]);
            *(float2*)(outp + (r + 8) * 64 + nh * 8 + t * 2) = make_float2(oa[m][2], oa[m][3]);
        }
    }
}

extern "C" void kernel_launch(void* const* d_in, const int* in_sizes, int n_in,
                              void* d_out, int out_size)
{
    const float* X  = (const float*)d_in[0];
    const float* Wk = (const float*)d_in[1];
    const float* Wq = (const float*)d_in[2];
    const float* Wv = (const float*)d_in[3];
    float* Out = (float*)d_out;

    const int nBatch = in_sizes[0] / 2048;

    cudaFuncSetAttribute(attn_kernel,
                         cudaFuncAttributeMaxDynamicSharedMemorySize, SMEM_BYTES);

    prep_weights<<<6, 256>>>(Wk, Wq, Wv);

    int grid = (nBatch + 7) / 8;
    attn_kernel<<<grid, THREADS, SMEM_BYTES>>>(X, Out, nBatch);
}